// round 13
// baseline (speedup 1.0000x reference)
#include <cuda_runtime.h>
#include <cuda_bf16.h>

// Problem dims
#define BN   4
#define SN   2048
#define HN   16
#define HDN  128
#define EN   2048

// Scratch (device globals: allocation-free)
__device__ float g_q[BN*HN*SN*HDN];     // [B,H,S,HD] projected q (pre-scaled by 1/sqrt(E))
__device__ float g_k[BN*HN*SN*HDN];
__device__ float g_v[BN*HN*SN*HDN];
__device__ float g_o[BN*SN*EN];         // attention output, [B*S, E]

// ---------------------------------------------------------------------------
// Helpers
// ---------------------------------------------------------------------------
__device__ __forceinline__ float f2tf(float x) {
    unsigned u;
    asm("cvt.rna.tf32.f32 %0, %1;" : "=r"(u) : "f"(x));
    return __uint_as_float(u);
}
__device__ __forceinline__ unsigned fu(float x) { return __float_as_uint(x); }

__device__ __forceinline__ void mma8(float c[4], const unsigned a[4], const unsigned b[2]) {
    asm volatile(
        "mma.sync.aligned.m16n8k8.row.col.f32.tf32.tf32.f32 "
        "{%0,%1,%2,%3},{%4,%5,%6,%7},{%8,%9},{%0,%1,%2,%3};"
        : "+f"(c[0]), "+f"(c[1]), "+f"(c[2]), "+f"(c[3])
        : "r"(a[0]), "r"(a[1]), "r"(a[2]), "r"(a[3]), "r"(b[0]), "r"(b[1]));
}

// A-fragment loader: 16 rows x 8 k from K-major f32 tile via ldmatrix.b16.x4
// (each 8x8 b16 matrix row = 16 bytes = 4 floats of one k-chunk).
// Yields a0=A[row0+g][k0+q], a1=A[row0+8+g][k0+q], a2=A[row0+g][k0+4+q],
// a3=A[row0+8+g][k0+4+q]  (g=lane/4, q=lane%4) — the m16n8k8 A layout.
__device__ __forceinline__ void ldsm_a(unsigned r[4], const float* tile, int ld,
                                       int row0, int k0) {
    int lane = threadIdx.x & 31;
    const float* p = tile + (row0 + (lane & 15)) * ld + k0 + ((lane >> 4) << 2);
    unsigned addr = (unsigned)__cvta_generic_to_shared(p);
    asm volatile("ldmatrix.sync.aligned.m8n8.x4.shared.b16 {%0,%1,%2,%3}, [%4];"
                 : "=r"(r[0]), "=r"(r[1]), "=r"(r[2]), "=r"(r[3]) : "r"(addr));
}

// B-fragment loader for TWO adjacent n8 tiles from K-major f32 tile:
// r0=b(tile0,klo), r1=b(tile0,khi), r2=b(tile1,klo), r3=b(tile1,khi)
__device__ __forceinline__ void ldsm_b2(unsigned r[4], const float* tile, int ld,
                                        int n0, int k0) {
    int lane = threadIdx.x & 31;
    const float* p = tile + (n0 + (lane & 7) + ((lane & 16) >> 1)) * ld
                   + k0 + ((lane & 8) >> 1);
    unsigned addr = (unsigned)__cvta_generic_to_shared(p);
    asm volatile("ldmatrix.sync.aligned.m8n8.x4.shared.b16 {%0,%1,%2,%3}, [%4];"
                 : "=r"(r[0]), "=r"(r[1]), "=r"(r[2]), "=r"(r[3]) : "r"(addr));
}

// ---------------------------------------------------------------------------
// QKV projection: Y[b,h,s,:] = X[b,s,h,:] @ W^T   (M=131072, N=128, K=128)
// Block 128x128, 8 warps (4m x 2n), warp tile 32x64.
// ---------------------------------------------------------------------------
#define PROJ_SMEM (2 * 128 * 132 * 4)

__global__ __launch_bounds__(256) void k_proj(const float* __restrict__ X,
                                              const float* __restrict__ W,
                                              int sel, float scale) {
    extern __shared__ float sm[];
    float* As = sm;                 // [128][132]
    float* Ws = sm + 128 * 132;     // [128][132]
    float* Y  = (sel == 0) ? g_q : (sel == 1) ? g_k : g_v;

    int tid = threadIdx.x;
    int rowbase = blockIdx.x * 128;

    for (int idx = tid; idx < 128 * 32; idx += 256) {
        int r = idx >> 5, c4 = (idx & 31) * 4;
        float4 xv = *(const float4*)(X + (size_t)(rowbase + r) * HDN + c4);
        float4 wv = *(const float4*)(W + r * HDN + c4);
        float* ad = As + r * 132 + c4;
        ad[0] = f2tf(xv.x * scale); ad[1] = f2tf(xv.y * scale);
        ad[2] = f2tf(xv.z * scale); ad[3] = f2tf(xv.w * scale);
        float* bd = Ws + r * 132 + c4;
        bd[0] = f2tf(wv.x); bd[1] = f2tf(wv.y);
        bd[2] = f2tf(wv.z); bd[3] = f2tf(wv.w);
    }
    __syncthreads();

    int lane = tid & 31, warp = tid >> 5;
    int g = lane >> 2, q = lane & 3;
    int wm = warp >> 1, wn = warp & 1;

    float acc[2][8][4];
    #pragma unroll
    for (int im = 0; im < 2; im++)
        #pragma unroll
        for (int jn = 0; jn < 8; jn++)
            #pragma unroll
            for (int t = 0; t < 4; t++) acc[im][jn][t] = 0.f;

    #pragma unroll
    for (int k0 = 0; k0 < 128; k0 += 8) {
        unsigned a[2][4], bb[8][2];
        ldsm_a(a[0], As, 132, wm * 32,      k0);
        ldsm_a(a[1], As, 132, wm * 32 + 16, k0);
        #pragma unroll
        for (int jp = 0; jp < 4; jp++) {
            unsigned r4[4];
            ldsm_b2(r4, Ws, 132, wn * 64 + jp * 16, k0);
            bb[2*jp][0] = r4[0]; bb[2*jp][1] = r4[1];
            bb[2*jp+1][0] = r4[2]; bb[2*jp+1][1] = r4[3];
        }
        #pragma unroll
        for (int im = 0; im < 2; im++)
            #pragma unroll
            for (int jn = 0; jn < 8; jn++) mma8(acc[im][jn], a[im], bb[jn]);
    }

    // Write to [B,H,S,HD]: input row r = (b*S+s)*H + h
    #pragma unroll
    for (int im = 0; im < 2; im++) {
        #pragma unroll
        for (int half = 0; half < 2; half++) {
            int rg = rowbase + wm * 32 + im * 16 + half * 8 + g;
            int h  = rg & 15;
            int bs = rg >> 4;
            int b_ = bs >> 11;
            int s  = bs & 2047;
            float* ob = Y + (((size_t)(b_ * HN + h)) * SN + s) * HDN;
            #pragma unroll
            for (int jn = 0; jn < 8; jn++) {
                int col = wn * 64 + jn * 8 + 2 * q;
                float2 v;
                v.x = acc[im][jn][half * 2 + 0];
                v.y = acc[im][jn][half * 2 + 1];
                *(float2*)(ob + col) = v;
            }
        }
    }
}

// ---------------------------------------------------------------------------
// Fused flash attention. Block = 128 queries, 8 warps, each warp owns
// 16 query rows x full 64-key width. Register-resident online softmax.
// K row-major; V stored TRANSPOSED (VT[d][k], ld=68) so PV B-fragments come
// from ldmatrix instead of 256 scalar LDS per warp per tile.
// ---------------------------------------------------------------------------
#define AT_LD 132
#define VT_LD 68
#define PS_LD 68
#define ATTN_SMEM ((128*AT_LD + 64*AT_LD + 128*VT_LD + 128*PS_LD + 64) * 4)

__global__ __launch_bounds__(256, 1) void k_attn(const int* __restrict__ mask) {
    extern __shared__ float sm[];
    float* Qs  = sm;                        // [128][132]  queries (tf32)
    float* Ks  = Qs + 128 * AT_LD;          // [64][132]   keys   [k][d]
    float* VT  = Ks + 64 * AT_LD;           // [128][68]   values transposed [d][k]
    float* Ps  = VT + 128 * VT_LD;          // [128][68]   probabilities (warp-private rows)
    float* msk = Ps + 128 * PS_LD;          // [64]        additive mask bias

    int tid = threadIdx.x, lane = tid & 31, warp = tid >> 5;
    int g = lane >> 2, q = lane & 3;
    int bh = blockIdx.y, qt = blockIdx.x, b = bh >> 4;
    int wrow = warp * 16;
    int dgrp = warp & 3, kslot = warp >> 2;
    int dcol = dgrp * 32 + lane;            // this thread's V d-column

    // Q fill (tf32)
    const float* qp = g_q + ((size_t)bh * SN + qt * 128) * HDN;
    for (int idx = tid; idx < 128 * 32; idx += 256) {
        int r = idx >> 5, c4 = (idx & 31) * 4;
        float4 v = *(const float4*)(qp + (size_t)r * HDN + c4);
        float* d = Qs + r * AT_LD + c4;
        d[0] = f2tf(v.x); d[1] = f2tf(v.y); d[2] = f2tf(v.z); d[3] = f2tf(v.w);
    }

    float oacc[16][4];
    #pragma unroll
    for (int jn = 0; jn < 16; jn++)
        #pragma unroll
        for (int t = 0; t < 4; t++) oacc[jn][t] = 0.f;

    float m0 = -1e30f, m1 = -1e30f, l0 = 0.f, l1 = 0.f;
    const int* mrow = mask + b * SN;

    for (int kt = 0; kt < 32; kt++) {
        // ---- prefetch K tile (row-major) + V tile (transpose-ready) ----
        const float* kp = g_k + ((size_t)bh * SN + kt * 64) * HDN;
        const float* vp = g_v + ((size_t)bh * SN + kt * 64) * HDN;
        float4 kr[8];
        #pragma unroll
        for (int i = 0; i < 8; i++) {
            int idx = tid + i * 256;
            int r = idx >> 5, c4 = (idx & 31) * 4;
            kr[i] = *(const float4*)(kp + (size_t)r * HDN + c4);
        }
        // V: thread owns d=dcol; per i, 4 consecutive k (coalesced across lanes)
        float vr[8][4];
        #pragma unroll
        for (int i = 0; i < 8; i++) {
            int kb = (2 * i + kslot) * 4;
            #pragma unroll
            for (int j = 0; j < 4; j++)
                vr[i][j] = vp[(size_t)(kb + j) * HDN + dcol];
        }
        int mraw = (tid < 64) ? mrow[kt * 64 + tid] : 1;

        __syncthreads();   // prior-iter consumers done before overwriting tiles

        #pragma unroll
        for (int i = 0; i < 8; i++) {
            int idx = tid + i * 256;
            int r = idx >> 5, c4 = (idx & 31) * 4;
            float* kd = Ks + r * AT_LD + c4;
            kd[0] = f2tf(kr[i].x); kd[1] = f2tf(kr[i].y);
            kd[2] = f2tf(kr[i].z); kd[3] = f2tf(kr[i].w);
        }
        {
            float* vt = VT + dcol * VT_LD;
            #pragma unroll
            for (int i = 0; i < 8; i++) {
                int kb = (2 * i + kslot) * 4;
                #pragma unroll
                for (int j = 0; j < 4; j++) vt[kb + j] = f2tf(vr[i][j]);
            }
        }
        if (tid < 64) msk[tid] = (mraw == 0) ? -1e20f : 0.f;
        __syncthreads();

        // ---- S = Q @ K^T : warp tile 16 x 64 ----
        float sacc[8][4];
        #pragma unroll
        for (int jn = 0; jn < 8; jn++)
            #pragma unroll
            for (int t = 0; t < 4; t++) sacc[jn][t] = 0.f;

        #pragma unroll
        for (int k0 = 0; k0 < 128; k0 += 8) {
            unsigned a[4], bb[8][2];
            ldsm_a(a, Qs, AT_LD, wrow, k0);
            #pragma unroll
            for (int jp = 0; jp < 4; jp++) {
                unsigned r4[4];
                ldsm_b2(r4, Ks, AT_LD, jp * 16, k0);
                bb[2*jp][0] = r4[0]; bb[2*jp][1] = r4[1];
                bb[2*jp+1][0] = r4[2]; bb[2*jp+1][1] = r4[3];
            }
            #pragma unroll
            for (int jn = 0; jn < 8; jn++) mma8(sacc[jn], a, bb[jn]);
        }

        // ---- register-resident online softmax (rows g and 8+g) ----
        float mx0 = -1e30f, mx1 = -1e30f;
        #pragma unroll
        for (int jn = 0; jn < 8; jn++) {
            float mka = msk[jn * 8 + 2 * q];
            float mkb = msk[jn * 8 + 2 * q + 1];
            sacc[jn][0] += mka; sacc[jn][1] += mkb;
            sacc[jn][2] += mka; sacc[jn][3] += mkb;
            mx0 = fmaxf(mx0, fmaxf(sacc[jn][0], sacc[jn][1]));
            mx1 = fmaxf(mx1, fmaxf(sacc[jn][2], sacc[jn][3]));
        }
        mx0 = fmaxf(mx0, __shfl_xor_sync(0xffffffffu, mx0, 1));
        mx0 = fmaxf(mx0, __shfl_xor_sync(0xffffffffu, mx0, 2));
        mx1 = fmaxf(mx1, __shfl_xor_sync(0xffffffffu, mx1, 1));
        mx1 = fmaxf(mx1, __shfl_xor_sync(0xffffffffu, mx1, 2));
        float mn0 = fmaxf(m0, mx0), mn1 = fmaxf(m1, mx1);

        float sum0 = 0.f, sum1 = 0.f;
        #pragma unroll
        for (int jn = 0; jn < 8; jn++) {
            float p00 = f2tf(__expf(sacc[jn][0] - mn0));
            float p01 = f2tf(__expf(sacc[jn][1] - mn0));
            float p10 = f2tf(__expf(sacc[jn][2] - mn1));
            float p11 = f2tf(__expf(sacc[jn][3] - mn1));
            sum0 += p00 + p01;
            sum1 += p10 + p11;
            int col = jn * 8 + 2 * q;
            float2 v0; v0.x = p00; v0.y = p01;
            float2 v1; v1.x = p10; v1.y = p11;
            *(float2*)(Ps + (wrow + g) * PS_LD + col)     = v0;
            *(float2*)(Ps + (wrow + 8 + g) * PS_LD + col) = v1;
        }
        sum0 += __shfl_xor_sync(0xffffffffu, sum0, 1);
        sum0 += __shfl_xor_sync(0xffffffffu, sum0, 2);
        sum1 += __shfl_xor_sync(0xffffffffu, sum1, 1);
        sum1 += __shfl_xor_sync(0xffffffffu, sum1, 2);

        float f0 = __expf(m0 - mn0), f1 = __expf(m1 - mn1);
        l0 = l0 * f0 + sum0;  l1 = l1 * f1 + sum1;
        m0 = mn0;  m1 = mn1;
        #pragma unroll
        for (int jn = 0; jn < 16; jn++) {
            oacc[jn][0] *= f0; oacc[jn][1] *= f0;
            oacc[jn][2] *= f1; oacc[jn][3] *= f1;
        }
        __syncwarp();

        // ---- O += P @ V : warp tile 16 x 128, all-LDSM operands ----
        #pragma unroll
        for (int kk = 0; kk < 64; kk += 8) {
            unsigned a[4];
            ldsm_a(a, Ps, PS_LD, wrow, kk);
            #pragma unroll
            for (int jp = 0; jp < 8; jp++) {
                unsigned r4[4], b0[2], b1[2];
                ldsm_b2(r4, VT, VT_LD, jp * 16, kk);
                b0[0] = r4[0]; b0[1] = r4[1];
                b1[0] = r4[2]; b1[1] = r4[3];
                mma8(oacc[2*jp],     a, b0);
                mma8(oacc[2*jp + 1], a, b1);
            }
        }
    }

    // Epilogue: divide by l, write to [B*S, E] (col = h*128 + d)
    float li0 = 1.0f / l0, li1 = 1.0f / l1;
    int row = b * SN + qt * 128 + wrow + g;
    float* ob = g_o + (size_t)row * EN + (bh & 15) * HDN;
    #pragma unroll
    for (int jn = 0; jn < 16; jn++) {
        int col = jn * 8 + 2 * q;
        float2 v0; v0.x = oacc[jn][0] * li0; v0.y = oacc[jn][1] * li0;
        float2 v1; v1.x = oacc[jn][2] * li1; v1.y = oacc[jn][3] * li1;
        *(float2*)(ob + col) = v0;
        *(float2*)(ob + (size_t)8 * EN + col) = v1;
    }
}

// ---------------------------------------------------------------------------
// Output GEMM: C[8192,2048] = g_o @ Wo^T + bo  (Wo K-major, directly usable)
// Block 128x128, K-chunk 64, 8 warps (4m x 2n), warp tile 32x64.
// ---------------------------------------------------------------------------
#define OUT_SMEM (2 * 128 * 68 * 4)

__global__ __launch_bounds__(256) void k_out(const float* __restrict__ Wo,
                                             const float* __restrict__ bo,
                                             float* __restrict__ C) {
    extern __shared__ float sm[];
    float* As = sm;             // [128][68]  (64 k-floats used per row)
    float* Bs = sm + 128 * 68;  // [128][68]
    int tid = threadIdx.x, lane = tid & 31, warp = tid >> 5;
    int g = lane >> 2, q = lane & 3;
    int wm = warp >> 1, wn = warp & 1;
    int e0 = blockIdx.x * 128;
    int m0 = blockIdx.y * 128;

    float acc[2][8][4];
    #pragma unroll
    for (int im = 0; im < 2; im++)
        #pragma unroll
        for (int jn = 0; jn < 8; jn++)
            #pragma unroll
            for (int t = 0; t < 4; t++) acc[im][jn][t] = 0.f;

    for (int kc = 0; kc < EN; kc += 64) {
        __syncthreads();
        for (int idx = tid; idx < 128 * 16; idx += 256) {
            int r = idx >> 4, c4 = (idx & 15) * 4;
            float4 av = *(const float4*)(g_o + (size_t)(m0 + r) * EN + kc + c4);
            float4 bv = *(const float4*)(Wo  + (size_t)(e0 + r) * EN + kc + c4);
            float* ad = As + r * 68 + c4;
            ad[0] = f2tf(av.x); ad[1] = f2tf(av.y); ad[2] = f2tf(av.z); ad[3] = f2tf(av.w);
            float* bd = Bs + r * 68 + c4;
            bd[0] = f2tf(bv.x); bd[1] = f2tf(bv.y); bd[2] = f2tf(bv.z); bd[3] = f2tf(bv.w);
        }
        __syncthreads();

        #pragma unroll
        for (int k0 = 0; k0 < 64; k0 += 8) {
            unsigned a[2][4], bb[8][2];
            ldsm_a(a[0], As, 68, wm * 32,      k0);
            ldsm_a(a[1], As, 68, wm * 32 + 16, k0);
            #pragma unroll
            for (int jp = 0; jp < 4; jp++) {
                unsigned r4[4];
                ldsm_b2(r4, Bs, 68, wn * 64 + jp * 16, k0);
                bb[2*jp][0] = r4[0]; bb[2*jp][1] = r4[1];
                bb[2*jp+1][0] = r4[2]; bb[2*jp+1][1] = r4[3];
            }
            #pragma unroll
            for (int im = 0; im < 2; im++)
                #pragma unroll
                for (int jn = 0; jn < 8; jn++) mma8(acc[im][jn], a[im], bb[jn]);
        }
    }

    #pragma unroll
    for (int im = 0; im < 2; im++) {
        int m = m0 + wm * 32 + im * 16 + g;
        #pragma unroll
        for (int jn = 0; jn < 8; jn++) {
            int e = e0 + wn * 64 + jn * 8 + 2 * q;
            float b0 = bo[e], b1 = bo[e + 1];
            float2 v0; v0.x = acc[im][jn][0] + b0; v0.y = acc[im][jn][1] + b1;
            float2 v1; v1.x = acc[im][jn][2] + b0; v1.y = acc[im][jn][3] + b1;
            *(float2*)(C + (size_t)m * EN + e)       = v0;
            *(float2*)(C + (size_t)(m + 8) * EN + e) = v1;
        }
    }
}

// ---------------------------------------------------------------------------
// Launch
// ---------------------------------------------------------------------------
extern "C" void kernel_launch(void* const* d_in, const int* in_sizes, int n_in,
                              void* d_out, int out_size) {
    const float* value  = (const float*)d_in[0];
    const float* key_in = (const float*)d_in[1];
    const float* query  = (const float*)d_in[2];
    const int*   mask   = (const int*)  d_in[3];
    const float* Wv     = (const float*)d_in[4];
    const float* Wk     = (const float*)d_in[5];
    const float* Wq     = (const float*)d_in[6];
    const float* Wo     = (const float*)d_in[7];
    const float* bo     = (const float*)d_in[8];
    float* out = (float*)d_out;

    cudaFuncSetAttribute(k_proj, cudaFuncAttributeMaxDynamicSharedMemorySize, PROJ_SMEM);
    cudaFuncSetAttribute(k_attn, cudaFuncAttributeMaxDynamicSharedMemorySize, ATTN_SMEM);
    cudaFuncSetAttribute(k_out,  cudaFuncAttributeMaxDynamicSharedMemorySize, OUT_SMEM);

    const float qscale = 0.022097086912079608f;   // 1/sqrt(2048)

    k_proj<<<1024, 256, PROJ_SMEM>>>(query,  Wq, 0, qscale);
    k_proj<<<1024, 256, PROJ_SMEM>>>(key_in, Wk, 1, 1.0f);
    k_proj<<<1024, 256, PROJ_SMEM>>>(value,  Wv, 2, 1.0f);

    k_attn<<<dim3(SN / 128, BN * HN), 256, ATTN_SMEM>>>(mask);

    k_out<<<dim3(EN / 128, (BN * SN) / 128), 256, OUT_SMEM>>>(Wo, bo, out);
}

// round 15
// speedup vs baseline: 1.0770x; 1.0770x over previous
#include <cuda_runtime.h>
#include <cuda_bf16.h>

// Problem dims
#define BN   4
#define SN   2048
#define HN   16
#define HDN  128
#define EN   2048

// Scratch (device globals: allocation-free)
__device__ float g_q[BN*HN*SN*HDN];     // [B,H,S,HD] projected q (pre-scaled by 1/sqrt(E))
__device__ float g_k[BN*HN*SN*HDN];
__device__ float g_v[BN*HN*SN*HDN];
__device__ float g_o[BN*SN*EN];         // attention output, [B*S, E]

// ---------------------------------------------------------------------------
// Helpers
// ---------------------------------------------------------------------------
__device__ __forceinline__ float f2tf(float x) {
    unsigned u;
    asm("cvt.rna.tf32.f32 %0, %1;" : "=r"(u) : "f"(x));
    return __uint_as_float(u);
}
__device__ __forceinline__ unsigned fu(float x) { return __float_as_uint(x); }

__device__ __forceinline__ void mma8(float c[4], const unsigned a[4], const unsigned b[2]) {
    asm volatile(
        "mma.sync.aligned.m16n8k8.row.col.f32.tf32.tf32.f32 "
        "{%0,%1,%2,%3},{%4,%5,%6,%7},{%8,%9},{%0,%1,%2,%3};"
        : "+f"(c[0]), "+f"(c[1]), "+f"(c[2]), "+f"(c[3])
        : "r"(a[0]), "r"(a[1]), "r"(a[2]), "r"(a[3]), "r"(b[0]), "r"(b[1]));
}

// A-fragment loader: 16 rows x 8 k from K-major f32 tile via ldmatrix.b16.x4.
__device__ __forceinline__ void ldsm_a(unsigned r[4], const float* tile, int ld,
                                       int row0, int k0) {
    int lane = threadIdx.x & 31;
    const float* p = tile + (row0 + (lane & 15)) * ld + k0 + ((lane >> 4) << 2);
    unsigned addr = (unsigned)__cvta_generic_to_shared(p);
    asm volatile("ldmatrix.sync.aligned.m8n8.x4.shared.b16 {%0,%1,%2,%3}, [%4];"
                 : "=r"(r[0]), "=r"(r[1]), "=r"(r[2]), "=r"(r[3]) : "r"(addr));
}

// B-fragment loader for TWO adjacent n8 tiles from K-major f32 tile.
__device__ __forceinline__ void ldsm_b2(unsigned r[4], const float* tile, int ld,
                                        int n0, int k0) {
    int lane = threadIdx.x & 31;
    const float* p = tile + (n0 + (lane & 7) + ((lane & 16) >> 1)) * ld
                   + k0 + ((lane & 8) >> 1);
    unsigned addr = (unsigned)__cvta_generic_to_shared(p);
    asm volatile("ldmatrix.sync.aligned.m8n8.x4.shared.b16 {%0,%1,%2,%3}, [%4];"
                 : "=r"(r[0]), "=r"(r[1]), "=r"(r[2]), "=r"(r[3]) : "r"(addr));
}

// ---------------------------------------------------------------------------
// QKV projection: Y[b,h,s,:] = X[b,s,h,:] @ W^T   (M=131072, N=128, K=128)
// Block 128x128, K-chunked (2 x 64) to halve smem -> 2 CTAs/SM.
// ---------------------------------------------------------------------------
#define PROJ_SMEM (2 * 128 * 68 * 4)

__global__ __launch_bounds__(256, 2) void k_proj(const float* __restrict__ X,
                                                 const float* __restrict__ W,
                                                 int sel, float scale) {
    extern __shared__ float sm[];
    float* As = sm;                 // [128][68]
    float* Ws = sm + 128 * 68;      // [128][68]
    float* Y  = (sel == 0) ? g_q : (sel == 1) ? g_k : g_v;

    int tid = threadIdx.x;
    int rowbase = blockIdx.x * 128;
    int lane = tid & 31, warp = tid >> 5;
    int g = lane >> 2, q = lane & 3;
    int wm = warp >> 1, wn = warp & 1;

    float acc[2][8][4];
    #pragma unroll
    for (int im = 0; im < 2; im++)
        #pragma unroll
        for (int jn = 0; jn < 8; jn++)
            #pragma unroll
            for (int t = 0; t < 4; t++) acc[im][jn][t] = 0.f;

    for (int ch = 0; ch < 2; ch++) {
        int kb = ch * 64;
        __syncthreads();
        for (int idx = tid; idx < 128 * 16; idx += 256) {
            int r = idx >> 4, c4 = (idx & 15) * 4;
            float4 xv = *(const float4*)(X + (size_t)(rowbase + r) * HDN + kb + c4);
            float4 wv = *(const float4*)(W + r * HDN + kb + c4);
            float* ad = As + r * 68 + c4;
            ad[0] = f2tf(xv.x * scale); ad[1] = f2tf(xv.y * scale);
            ad[2] = f2tf(xv.z * scale); ad[3] = f2tf(xv.w * scale);
            float* bd = Ws + r * 68 + c4;
            bd[0] = f2tf(wv.x); bd[1] = f2tf(wv.y);
            bd[2] = f2tf(wv.z); bd[3] = f2tf(wv.w);
        }
        __syncthreads();

        #pragma unroll
        for (int k0 = 0; k0 < 64; k0 += 8) {
            unsigned a[2][4], bb[8][2];
            ldsm_a(a[0], As, 68, wm * 32,      k0);
            ldsm_a(a[1], As, 68, wm * 32 + 16, k0);
            #pragma unroll
            for (int jp = 0; jp < 4; jp++) {
                unsigned r4[4];
                ldsm_b2(r4, Ws, 68, wn * 64 + jp * 16, k0);
                bb[2*jp][0] = r4[0]; bb[2*jp][1] = r4[1];
                bb[2*jp+1][0] = r4[2]; bb[2*jp+1][1] = r4[3];
            }
            #pragma unroll
            for (int im = 0; im < 2; im++)
                #pragma unroll
                for (int jn = 0; jn < 8; jn++) mma8(acc[im][jn], a[im], bb[jn]);
        }
    }

    // Write to [B,H,S,HD]: input row r = (b*S+s)*H + h
    #pragma unroll
    for (int im = 0; im < 2; im++) {
        #pragma unroll
        for (int half = 0; half < 2; half++) {
            int rg = rowbase + wm * 32 + im * 16 + half * 8 + g;
            int h  = rg & 15;
            int bs = rg >> 4;
            int b_ = bs >> 11;
            int s  = bs & 2047;
            float* ob = Y + (((size_t)(b_ * HN + h)) * SN + s) * HDN;
            #pragma unroll
            for (int jn = 0; jn < 8; jn++) {
                int col = wn * 64 + jn * 8 + 2 * q;
                float2 v;
                v.x = acc[im][jn][half * 2 + 0];
                v.y = acc[im][jn][half * 2 + 1];
                *(float2*)(ob + col) = v;
            }
        }
    }
}

// ---------------------------------------------------------------------------
// Fused flash attention. Block = 128 queries, 8 warps x (16q x 64k).
// Q A-fragments hoisted to registers (loaded once). K/VT/msk double-buffered:
// one barrier per key tile; global loads hidden under compute.
// ---------------------------------------------------------------------------
#define AT_LD 132
#define VT_LD 68
#define PS_LD 68
#define ATTN_SMEM ((2*64*AT_LD + 2*128*VT_LD + 128*PS_LD + 128) * 4)

__global__ __launch_bounds__(256, 1) void k_attn(const int* __restrict__ mask) {
    extern __shared__ float sm[];
    float* Ks0 = sm;                        // [64][132] stage 0 keys
    float* Ks1 = Ks0 + 64 * AT_LD;          // [64][132] stage 1 keys
    float* VT0 = Ks1 + 64 * AT_LD;          // [128][68] stage 0 V^T
    float* VT1 = VT0 + 128 * VT_LD;         // [128][68] stage 1 V^T
    float* Ps  = VT1 + 128 * VT_LD;         // [128][68] probabilities (warp-private)
    float* msk = Ps + 128 * PS_LD;          // [2][64]   additive mask bias

    int tid = threadIdx.x, lane = tid & 31, warp = tid >> 5;
    int g = lane >> 2, q = lane & 3;
    int bh = blockIdx.y, qt = blockIdx.x, b = bh >> 4;
    int wrow = warp * 16;
    int dgrp = warp & 3, kslot = warp >> 2;
    int dcol = dgrp * 32 + lane;            // this thread's V d-column

    const int* mrow = mask + b * SN;

    // ---- stage Q through the two K buffers, then hoist A-frags to regs ----
    const float* qp = g_q + ((size_t)bh * SN + qt * 128) * HDN;
    for (int idx = tid; idx < 128 * 32; idx += 256) {
        int r = idx >> 5, c4 = (idx & 31) * 4;
        float4 v = *(const float4*)(qp + (size_t)r * HDN + c4);
        float* d = ((r < 64) ? Ks0 + r * AT_LD : Ks1 + (r - 64) * AT_LD) + c4;
        d[0] = f2tf(v.x); d[1] = f2tf(v.y); d[2] = f2tf(v.z); d[3] = f2tf(v.w);
    }
    __syncthreads();

    unsigned qf[16][4];
    {
        const float* qsrc = (warp < 4) ? Ks0 : Ks1;
        int qr = (warp & 3) * 16;
        #pragma unroll
        for (int kq = 0; kq < 16; kq++) ldsm_a(qf[kq], qsrc, AT_LD, qr, kq * 8);
    }
    __syncthreads();   // all Q frags read; K buffers reusable

    // ---- prologue: fill stage 0 with tile 0 ----
    {
        const float* kp = g_k + ((size_t)bh * SN) * HDN;
        const float* vp = g_v + ((size_t)bh * SN) * HDN;
        for (int i = 0; i < 8; i++) {
            int idx = tid + i * 256;
            int r = idx >> 5, c4 = (idx & 31) * 4;
            float4 kv = *(const float4*)(kp + (size_t)r * HDN + c4);
            float* kd = Ks0 + r * AT_LD + c4;
            kd[0] = f2tf(kv.x); kd[1] = f2tf(kv.y);
            kd[2] = f2tf(kv.z); kd[3] = f2tf(kv.w);
        }
        float* vt = VT0 + dcol * VT_LD;
        for (int i = 0; i < 8; i++) {
            int kb = (2 * i + kslot) * 4;
            #pragma unroll
            for (int j = 0; j < 4; j++)
                vt[kb + j] = f2tf(vp[(size_t)(kb + j) * HDN + dcol]);
        }
        if (tid < 64) msk[tid] = (mrow[tid] == 0) ? -1e20f : 0.f;
    }
    __syncthreads();

    float oacc[16][4];
    #pragma unroll
    for (int jn = 0; jn < 16; jn++)
        #pragma unroll
        for (int t = 0; t < 4; t++) oacc[jn][t] = 0.f;

    float m0 = -1e30f, m1 = -1e30f, l0 = 0.f, l1 = 0.f;

    for (int kt = 0; kt < 32; kt++) {
        int s = kt & 1, sn = s ^ 1;
        const float* Kst = s ? Ks1 : Ks0;
        const float* Vst = s ? VT1 : VT0;
        float* Ksn = sn ? Ks1 : Ks0;
        float* Vsn = sn ? VT1 : VT0;
        const float* mskc = msk + s * 64;
        bool pf = (kt < 31);

        // ---- prefetch K for tile kt+1 (lands under QK) ----
        float4 kr[8];
        int mraw = 1;
        if (pf) {
            const float* kp = g_k + ((size_t)bh * SN + (kt + 1) * 64) * HDN;
            #pragma unroll
            for (int i = 0; i < 8; i++) {
                int idx = tid + i * 256;
                int r = idx >> 5, c4 = (idx & 31) * 4;
                kr[i] = *(const float4*)(kp + (size_t)r * HDN + c4);
            }
            if (tid < 64) mraw = mrow[(kt + 1) * 64 + tid];
        }

        // ---- S = Q @ K^T : warp tile 16 x 64 (Q frags from registers) ----
        float sacc[8][4];
        #pragma unroll
        for (int jn = 0; jn < 8; jn++)
            #pragma unroll
            for (int t = 0; t < 4; t++) sacc[jn][t] = 0.f;

        #pragma unroll
        for (int kq = 0; kq < 16; kq++) {
            int k0 = kq * 8;
            unsigned bb[8][2];
            #pragma unroll
            for (int jp = 0; jp < 4; jp++) {
                unsigned r4[4];
                ldsm_b2(r4, Kst, AT_LD, jp * 16, k0);
                bb[2*jp][0] = r4[0]; bb[2*jp][1] = r4[1];
                bb[2*jp+1][0] = r4[2]; bb[2*jp+1][1] = r4[3];
            }
            #pragma unroll
            for (int jn = 0; jn < 8; jn++) mma8(sacc[jn], qf[kq], bb[jn]);
        }

        // ---- drain K prefetch into next stage; start V prefetch ----
        float vr[8][4];
        if (pf) {
            #pragma unroll
            for (int i = 0; i < 8; i++) {
                int idx = tid + i * 256;
                int r = idx >> 5, c4 = (idx & 31) * 4;
                float* kd = Ksn + r * AT_LD + c4;
                kd[0] = f2tf(kr[i].x); kd[1] = f2tf(kr[i].y);
                kd[2] = f2tf(kr[i].z); kd[3] = f2tf(kr[i].w);
            }
            if (tid < 64) msk[sn * 64 + tid] = (mraw == 0) ? -1e20f : 0.f;
            const float* vp = g_v + ((size_t)bh * SN + (kt + 1) * 64) * HDN;
            #pragma unroll
            for (int i = 0; i < 8; i++) {
                int kb = (2 * i + kslot) * 4;
                #pragma unroll
                for (int j = 0; j < 4; j++)
                    vr[i][j] = vp[(size_t)(kb + j) * HDN + dcol];
            }
        }

        // ---- register-resident online softmax (rows g and 8+g) ----
        float mx0 = -1e30f, mx1 = -1e30f;
        #pragma unroll
        for (int jn = 0; jn < 8; jn++) {
            float mka = mskc[jn * 8 + 2 * q];
            float mkb = mskc[jn * 8 + 2 * q + 1];
            sacc[jn][0] += mka; sacc[jn][1] += mkb;
            sacc[jn][2] += mka; sacc[jn][3] += mkb;
            mx0 = fmaxf(mx0, fmaxf(sacc[jn][0], sacc[jn][1]));
            mx1 = fmaxf(mx1, fmaxf(sacc[jn][2], sacc[jn][3]));
        }
        mx0 = fmaxf(mx0, __shfl_xor_sync(0xffffffffu, mx0, 1));
        mx0 = fmaxf(mx0, __shfl_xor_sync(0xffffffffu, mx0, 2));
        mx1 = fmaxf(mx1, __shfl_xor_sync(0xffffffffu, mx1, 1));
        mx1 = fmaxf(mx1, __shfl_xor_sync(0xffffffffu, mx1, 2));
        float mn0 = fmaxf(m0, mx0), mn1 = fmaxf(m1, mx1);

        float sum0 = 0.f, sum1 = 0.f;
        #pragma unroll
        for (int jn = 0; jn < 8; jn++) {
            float p00 = f2tf(__expf(sacc[jn][0] - mn0));
            float p01 = f2tf(__expf(sacc[jn][1] - mn0));
            float p10 = f2tf(__expf(sacc[jn][2] - mn1));
            float p11 = f2tf(__expf(sacc[jn][3] - mn1));
            sum0 += p00 + p01;
            sum1 += p10 + p11;
            int col = jn * 8 + 2 * q;
            float2 v0; v0.x = p00; v0.y = p01;
            float2 v1; v1.x = p10; v1.y = p11;
            *(float2*)(Ps + (wrow + g) * PS_LD + col)     = v0;
            *(float2*)(Ps + (wrow + 8 + g) * PS_LD + col) = v1;
        }
        sum0 += __shfl_xor_sync(0xffffffffu, sum0, 1);
        sum0 += __shfl_xor_sync(0xffffffffu, sum0, 2);
        sum1 += __shfl_xor_sync(0xffffffffu, sum1, 1);
        sum1 += __shfl_xor_sync(0xffffffffu, sum1, 2);

        float f0 = __expf(m0 - mn0), f1 = __expf(m1 - mn1);
        l0 = l0 * f0 + sum0;  l1 = l1 * f1 + sum1;
        m0 = mn0;  m1 = mn1;
        #pragma unroll
        for (int jn = 0; jn < 16; jn++) {
            oacc[jn][0] *= f0; oacc[jn][1] *= f0;
            oacc[jn][2] *= f1; oacc[jn][3] *= f1;
        }
        __syncwarp();

        // ---- O += P @ V : warp tile 16 x 128, all-LDSM operands ----
        #pragma unroll
        for (int kk = 0; kk < 64; kk += 8) {
            unsigned a[4];
            ldsm_a(a, Ps, PS_LD, wrow, kk);
            #pragma unroll
            for (int jp = 0; jp < 8; jp++) {
                unsigned r4[4], b0[2], b1[2];
                ldsm_b2(r4, Vst, VT_LD, jp * 16, kk);
                b0[0] = r4[0]; b0[1] = r4[1];
                b1[0] = r4[2]; b1[1] = r4[3];
                mma8(oacc[2*jp],     a, b0);
                mma8(oacc[2*jp + 1], a, b1);
            }
        }

        // ---- drain V prefetch into next stage ----
        if (pf) {
            float* vt = Vsn + dcol * VT_LD;
            #pragma unroll
            for (int i = 0; i < 8; i++) {
                int kb = (2 * i + kslot) * 4;
                #pragma unroll
                for (int j = 0; j < 4; j++) vt[kb + j] = f2tf(vr[i][j]);
            }
        }
        __syncthreads();
    }

    // Epilogue: divide by l, write to [B*S, E] (col = h*128 + d)
    float li0 = 1.0f / l0, li1 = 1.0f / l1;
    int row = b * SN + qt * 128 + wrow + g;
    float* ob = g_o + (size_t)row * EN + (bh & 15) * HDN;
    #pragma unroll
    for (int jn = 0; jn < 16; jn++) {
        int col = jn * 8 + 2 * q;
        float2 v0; v0.x = oacc[jn][0] * li0; v0.y = oacc[jn][1] * li0;
        float2 v1; v1.x = oacc[jn][2] * li1; v1.y = oacc[jn][3] * li1;
        *(float2*)(ob + col) = v0;
        *(float2*)(ob + (size_t)8 * EN + col) = v1;
    }
}

// ---------------------------------------------------------------------------
// Output GEMM: C[8192,2048] = g_o @ Wo^T + bo  (Wo K-major, directly usable)
// Block 128x128, K-chunk 64, double-buffered: prefetch -> compute -> store.
// ---------------------------------------------------------------------------
#define OUT_SMEM (4 * 128 * 68 * 4)

__global__ __launch_bounds__(256) void k_out(const float* __restrict__ Wo,
                                             const float* __restrict__ bo,
                                             float* __restrict__ C) {
    extern __shared__ float sm[];
    float* As0 = sm;                 // [128][68] stage 0 A
    float* As1 = As0 + 128 * 68;     // [128][68] stage 1 A
    float* Bs0 = As1 + 128 * 68;     // [128][68] stage 0 B
    float* Bs1 = Bs0 + 128 * 68;     // [128][68] stage 1 B
    int tid = threadIdx.x, lane = tid & 31, warp = tid >> 5;
    int g = lane >> 2, q = lane & 3;
    int wm = warp >> 1, wn = warp & 1;
    int e0 = blockIdx.x * 128;
    int m0 = blockIdx.y * 128;

    float acc[2][8][4];
    #pragma unroll
    for (int im = 0; im < 2; im++)
        #pragma unroll
        for (int jn = 0; jn < 8; jn++)
            #pragma unroll
            for (int t = 0; t < 4; t++) acc[im][jn][t] = 0.f;

    // prologue: fill stage 0 with chunk 0
    for (int idx = tid; idx < 128 * 16; idx += 256) {
        int r = idx >> 4, c4 = (idx & 15) * 4;
        float4 av = *(const float4*)(g_o + (size_t)(m0 + r) * EN + c4);
        float4 bv = *(const float4*)(Wo  + (size_t)(e0 + r) * EN + c4);
        float* ad = As0 + r * 68 + c4;
        ad[0] = f2tf(av.x); ad[1] = f2tf(av.y); ad[2] = f2tf(av.z); ad[3] = f2tf(av.w);
        float* bd = Bs0 + r * 68 + c4;
        bd[0] = f2tf(bv.x); bd[1] = f2tf(bv.y); bd[2] = f2tf(bv.z); bd[3] = f2tf(bv.w);
    }
    __syncthreads();

    for (int c = 0; c < 32; c++) {
        int s = c & 1, sn = s ^ 1;
        const float* Asc = s ? As1 : As0;
        const float* Bsc = s ? Bs1 : Bs0;
        float* Asn = sn ? As1 : As0;
        float* Bsn = sn ? Bs1 : Bs0;
        bool pf = (c < 31);

        // prefetch next chunk into registers (lands under compute)
        float4 av[4], bv[4];
        if (pf) {
            int kc = (c + 1) * 64;
            #pragma unroll
            for (int i = 0; i < 4; i++) {
                int idx = tid + i * 256;
                int r = idx >> 3, c4 = (idx & 7) * 8;  // 8 float4 rows? see below
                // 128*16 float4 over 256 threads x 8? -> use 8 iterations of float4
                (void)r; (void)c4;
            }
            // NOTE: actual prefetch below (8 float4 per thread covers A and B)
            #pragma unroll
            for (int i = 0; i < 4; i++) {
                int idx = tid + i * 256;
                int r = idx >> 4, c4 = (idx & 15) * 4;
                av[i] = *(const float4*)(g_o + (size_t)(m0 + r) * EN + kc + c4);
                bv[i] = *(const float4*)(Wo  + (size_t)(e0 + r) * EN + kc + c4);
            }
        }

        // compute chunk c
        #pragma unroll
        for (int k0 = 0; k0 < 64; k0 += 8) {
            unsigned a[2][4], bb[8][2];
            ldsm_a(a[0], Asc, 68, wm * 32,      k0);
            ldsm_a(a[1], Asc, 68, wm * 32 + 16, k0);
            #pragma unroll
            for (int jp = 0; jp < 4; jp++) {
                unsigned r4[4];
                ldsm_b2(r4, Bsc, 68, wn * 64 + jp * 16, k0);
                bb[2*jp][0] = r4[0]; bb[2*jp][1] = r4[1];
                bb[2*jp+1][0] = r4[2]; bb[2*jp+1][1] = r4[3];
            }
            #pragma unroll
            for (int im = 0; im < 2; im++)
                #pragma unroll
                for (int jn = 0; jn < 8; jn++) mma8(acc[im][jn], a[im], bb[jn]);
        }

        // second half of prefetch (rows 64..127) + store all to next stage
        if (pf) {
            int kc = (c + 1) * 64;
            float4 av2[4], bv2[4];
            #pragma unroll
            for (int i = 0; i < 4; i++) {
                int idx = tid + (i + 4) * 256;
                int r = idx >> 4, c4 = (idx & 15) * 4;
                av2[i] = *(const float4*)(g_o + (size_t)(m0 + r) * EN + kc + c4);
                bv2[i] = *(const float4*)(Wo  + (size_t)(e0 + r) * EN + kc + c4);
            }
            #pragma unroll
            for (int i = 0; i < 4; i++) {
                int idx = tid + i * 256;
                int r = idx >> 4, c4 = (idx & 15) * 4;
                float* ad = Asn + r * 68 + c4;
                ad[0] = f2tf(av[i].x); ad[1] = f2tf(av[i].y);
                ad[2] = f2tf(av[i].z); ad[3] = f2tf(av[i].w);
                float* bd = Bsn + r * 68 + c4;
                bd[0] = f2tf(bv[i].x); bd[1] = f2tf(bv[i].y);
                bd[2] = f2tf(bv[i].z); bd[3] = f2tf(bv[i].w);
            }
            #pragma unroll
            for (int i = 0; i < 4; i++) {
                int idx = tid + (i + 4) * 256;
                int r = idx >> 4, c4 = (idx & 15) * 4;
                float* ad = Asn + r * 68 + c4;
                ad[0] = f2tf(av2[i].x); ad[1] = f2tf(av2[i].y);
                ad[2] = f2tf(av2[i].z); ad[3] = f2tf(av2[i].w);
                float* bd = Bsn + r * 68 + c4;
                bd[0] = f2tf(bv2[i].x); bd[1] = f2tf(bv2[i].y);
                bd[2] = f2tf(bv2[i].z); bd[3] = f2tf(bv2[i].w);
            }
        }
        __syncthreads();
    }

    #pragma unroll
    for (int im = 0; im < 2; im++) {
        int m = m0 + wm * 32 + im * 16 + g;
        #pragma unroll
        for (int jn = 0; jn < 8; jn++) {
            int e = e0 + wn * 64 + jn * 8 + 2 * q;
            float b0 = bo[e], b1 = bo[e + 1];
            float2 v0; v0.x = acc[im][jn][0] + b0; v0.y = acc[im][jn][1] + b1;
            float2 v1; v1.x = acc[im][jn][2] + b0; v1.y = acc[im][jn][3] + b1;
            *(float2*)(C + (size_t)m * EN + e)       = v0;
            *(float2*)(C + (size_t)(m + 8) * EN + e) = v1;
        }
    }
}

// ---------------------------------------------------------------------------
// Launch
// ---------------------------------------------------------------------------
extern "C" void kernel_launch(void* const* d_in, const int* in_sizes, int n_in,
                              void* d_out, int out_size) {
    const float* value  = (const float*)d_in[0];
    const float* key_in = (const float*)d_in[1];
    const float* query  = (const float*)d_in[2];
    const int*   mask   = (const int*)  d_in[3];
    const float* Wv     = (const float*)d_in[4];
    const float* Wk     = (const float*)d_in[5];
    const float* Wq     = (const float*)d_in[6];
    const float* Wo     = (const float*)d_in[7];
    const float* bo     = (const float*)d_in[8];
    float* out = (float*)d_out;

    cudaFuncSetAttribute(k_proj, cudaFuncAttributeMaxDynamicSharedMemorySize, PROJ_SMEM);
    cudaFuncSetAttribute(k_attn, cudaFuncAttributeMaxDynamicSharedMemorySize, ATTN_SMEM);
    cudaFuncSetAttribute(k_out,  cudaFuncAttributeMaxDynamicSharedMemorySize, OUT_SMEM);

    const float qscale = 0.022097086912079608f;   // 1/sqrt(2048)

    k_proj<<<1024, 256, PROJ_SMEM>>>(query,  Wq, 0, qscale);
    k_proj<<<1024, 256, PROJ_SMEM>>>(key_in, Wk, 1, 1.0f);
    k_proj<<<1024, 256, PROJ_SMEM>>>(value,  Wv, 2, 1.0f);

    k_attn<<<dim3(SN / 128, BN * HN), 256, ATTN_SMEM>>>(mask);

    k_out<<<dim3(EN / 128, (BN * SN) / 128), 256, OUT_SMEM>>>(Wo, bo, out);
}